// round 6
// baseline (speedup 1.0000x reference)
#include <cuda_runtime.h>
#include <math.h>

#define NB 32
#define NS 8192
#define ND 256
#define NCHUNK 32          // blocks per batch in main pass
#define POS_PER_BLOCK 256  // 8 warps * 32 positions
#define POS_PER_WARP 32

// ---------------- scratch (no allocation allowed) ----------------
__device__ float g_V[NB * ND];             // v[b] = Wa_w^T ht[b]
__device__ float g_c0[NB];                 // ht[b] . Wa_b
__device__ float g_PM[NB * NCHUNK];        // per-block partial max
__device__ float g_PL[NB * NCHUNK];        // per-block partial sum
__device__ float g_PA[NB * NCHUNK * ND];   // per-block partial weighted row-sum

// ---------------- K1: v[b] = Wa_w^T ht[b], c0[b] = ht.Wa_b ---------------
// One block per batch, 1024 threads: 4 d-groups x 64, folded in smem.
__global__ void __launch_bounds__(1024)
k_pre(const float* __restrict__ ht,
      const float* __restrict__ Wa_w,
      const float* __restrict__ Wa_b) {
    int b = blockIdx.x;
    int t = threadIdx.x;
    int col = t & 255;
    int grp = t >> 8;            // 0..3, handles d in [grp*64, grp*64+64)

    __shared__ float sh[ND];
    __shared__ float sp[4][ND];
    __shared__ float red[ND];
    if (t < ND) sh[t] = ht[b * ND + t];
    __syncthreads();

    const float* Wp = Wa_w + (size_t)(grp * 64) * ND + col;
    float a0 = 0.f, a1 = 0.f, a2 = 0.f, a3 = 0.f;
    #pragma unroll 4
    for (int d = 0; d < 64; d += 4) {          // 4 chains, 16 loads/chain window
        float w0 = Wp[(size_t)(d + 0) * ND];
        float w1 = Wp[(size_t)(d + 1) * ND];
        float w2 = Wp[(size_t)(d + 2) * ND];
        float w3 = Wp[(size_t)(d + 3) * ND];
        a0 = fmaf(sh[grp * 64 + d + 0], w0, a0);
        a1 = fmaf(sh[grp * 64 + d + 1], w1, a1);
        a2 = fmaf(sh[grp * 64 + d + 2], w2, a2);
        a3 = fmaf(sh[grp * 64 + d + 3], w3, a3);
    }
    sp[grp][col] = (a0 + a1) + (a2 + a3);

    if (t < ND) red[t] = sh[t] * Wa_b[t];
    __syncthreads();

    if (t < ND) {
        g_V[b * ND + t] = sp[0][t] + sp[1][t] + sp[2][t] + sp[3][t];
    }
    if (t < 128) {
        red[t] += red[t + 128];
        __syncwarp(0xffffffffu);
    }
    __syncthreads();
    if (t < 32) {
        float r = red[t] + red[t + 32] + red[t + 64] + red[t + 96];
        #pragma unroll
        for (int o = 16; o > 0; o >>= 1)
            r += __shfl_xor_sync(0xffffffffu, r, o);
        if (t == 0) g_c0[b] = r;
    }
}

// ---------------- K2: fused energy + online softmax + weighted row-sum ----
// 4 rows per warp-iteration, 8 LDG.128/lane (MLP 8), 4-way ILP shuffle reduce.
__global__ void __launch_bounds__(256, 4)
k_main(const float* __restrict__ hs, const int* __restrict__ slen,
       float* __restrict__ alpha /* energy staging = d_out alpha region */) {
    int chunk = blockIdx.x, b = blockIdx.y;
    int tid = threadIdx.x, w = tid >> 5, lane = tid & 31;
    int len = slen[b];
    int len_eff = (len == 0) ? NS : len;    // len==0: uniform softmax, full work

    if (chunk * POS_PER_BLOCK >= len_eff) return;

    float c0 = g_c0[b];
    const float4* v4 = (const float4*)(g_V + b * ND);
    float4 va = v4[lane], vb = v4[lane + 32];

    int s0 = chunk * POS_PER_BLOCK + w * POS_PER_WARP;
    bool active = (s0 < len_eff);

    float M = -1e30f, Lsum = 0.f;
    float4 Aa = make_float4(0.f, 0.f, 0.f, 0.f);
    float4 Ab = make_float4(0.f, 0.f, 0.f, 0.f);

    if (active) {
        const float4* row = (const float4*)(hs + ((size_t)b * NS + s0) * ND);
        #pragma unroll 1
        for (int i = 0; i < POS_PER_WARP / 4; i++) {
            const float4* r = row + i * 4 * 64;      // row pitch = 64 float4
            // 8 independent LDG.128 per lane
            float4 r0a = r[lane],            r0b = r[lane + 32];
            float4 r1a = r[64 + lane],       r1b = r[64 + lane + 32];
            float4 r2a = r[128 + lane],      r2b = r[128 + lane + 32];
            float4 r3a = r[192 + lane],      r3b = r[192 + lane + 32];

            float p0 = r0a.x*va.x + r0a.y*va.y + r0a.z*va.z + r0a.w*va.w
                     + r0b.x*vb.x + r0b.y*vb.y + r0b.z*vb.z + r0b.w*vb.w;
            float p1 = r1a.x*va.x + r1a.y*va.y + r1a.z*va.z + r1a.w*va.w
                     + r1b.x*vb.x + r1b.y*vb.y + r1b.z*vb.z + r1b.w*vb.w;
            float p2 = r2a.x*va.x + r2a.y*va.y + r2a.z*va.z + r2a.w*va.w
                     + r2b.x*vb.x + r2b.y*vb.y + r2b.z*vb.z + r2b.w*vb.w;
            float p3 = r3a.x*va.x + r3a.y*va.y + r3a.z*va.z + r3a.w*va.w
                     + r3b.x*vb.x + r3b.y*vb.y + r3b.z*vb.z + r3b.w*vb.w;
            #pragma unroll
            for (int o = 16; o > 0; o >>= 1) {       // 4 independent chains
                p0 += __shfl_xor_sync(0xffffffffu, p0, o);
                p1 += __shfl_xor_sync(0xffffffffu, p1, o);
                p2 += __shfl_xor_sync(0xffffffffu, p2, o);
                p3 += __shfl_xor_sync(0xffffffffu, p3, o);
            }
            int s = s0 + 4 * i;
            float e0 = p0 + c0, e1 = p1 + c0, e2 = p2 + c0, e3 = p3 + c0;
            e0 = (e0 > 0.f) ? e0 : 0.2f * e0;        // leaky relu
            e1 = (e1 > 0.f) ? e1 : 0.2f * e1;
            e2 = (e2 > 0.f) ? e2 : 0.2f * e2;
            e3 = (e3 > 0.f) ? e3 : 0.2f * e3;
            if (s + 0 >= len) e0 = -10000.f;         // length mask (real len)
            if (s + 1 >= len) e1 = -10000.f;
            if (s + 2 >= len) e2 = -10000.f;
            if (s + 3 >= len) e3 = -10000.f;
            if (lane == 0)
                *(float4*)(alpha + (size_t)b * NS + s) = make_float4(e0, e1, e2, e3);

            float Mn = fmaxf(fmaxf(M, fmaxf(e0, e1)), fmaxf(e2, e3));
            float scale = __expf(M - Mn);
            float q0 = __expf(e0 - Mn), q1 = __expf(e1 - Mn);
            float q2 = __expf(e2 - Mn), q3 = __expf(e3 - Mn);
            Lsum = Lsum * scale + (q0 + q1) + (q2 + q3);
            Aa.x = fmaf(q3,r3a.x, fmaf(q2,r2a.x, fmaf(q1,r1a.x, fmaf(q0,r0a.x, Aa.x*scale))));
            Aa.y = fmaf(q3,r3a.y, fmaf(q2,r2a.y, fmaf(q1,r1a.y, fmaf(q0,r0a.y, Aa.y*scale))));
            Aa.z = fmaf(q3,r3a.z, fmaf(q2,r2a.z, fmaf(q1,r1a.z, fmaf(q0,r0a.z, Aa.z*scale))));
            Aa.w = fmaf(q3,r3a.w, fmaf(q2,r2a.w, fmaf(q1,r1a.w, fmaf(q0,r0a.w, Aa.w*scale))));
            Ab.x = fmaf(q3,r3b.x, fmaf(q2,r2b.x, fmaf(q1,r1b.x, fmaf(q0,r0b.x, Ab.x*scale))));
            Ab.y = fmaf(q3,r3b.y, fmaf(q2,r2b.y, fmaf(q1,r1b.y, fmaf(q0,r0b.y, Ab.y*scale))));
            Ab.z = fmaf(q3,r3b.z, fmaf(q2,r2b.z, fmaf(q1,r1b.z, fmaf(q0,r0b.z, Ab.z*scale))));
            Ab.w = fmaf(q3,r3b.w, fmaf(q2,r2b.w, fmaf(q1,r1b.w, fmaf(q0,r0b.w, Ab.w*scale))));
            M = Mn;
        }
    }

    // combine 8 warps within the block
    __shared__ float sM[8], sL[8];
    __shared__ float sA[8][ND];
    float* arow = sA[w];
    arow[lane * 4 + 0] = Aa.x; arow[lane * 4 + 1] = Aa.y;
    arow[lane * 4 + 2] = Aa.z; arow[lane * 4 + 3] = Aa.w;
    arow[128 + lane * 4 + 0] = Ab.x; arow[128 + lane * 4 + 1] = Ab.y;
    arow[128 + lane * 4 + 2] = Ab.z; arow[128 + lane * 4 + 3] = Ab.w;
    if (lane == 0) { sM[w] = M; sL[w] = Lsum; }
    __syncthreads();

    float Mb = sM[0];
    #pragma unroll
    for (int j = 1; j < 8; j++) Mb = fmaxf(Mb, sM[j]);
    float acc = 0.f, lb = 0.f;
    #pragma unroll
    for (int j = 0; j < 8; j++) {
        float sc = __expf(sM[j] - Mb);   // sM=-1e30 (inactive warp) -> 0
        acc = fmaf(sc, sA[j][tid], acc);
        lb = fmaf(sc, sL[j], lb);
    }
    int pid = b * NCHUNK + chunk;
    g_PA[pid * ND + tid] = acc;
    if (tid == 0) { g_PM[pid] = Mb; g_PL[pid] = lb; }
}

// ---------------- K3: combine + context GEMV + alpha normalize -----------
__global__ void __launch_bounds__(256)
k_fin(const float* __restrict__ Wc_w, const float* __restrict__ Wc_b,
      const int* __restrict__ slen, float* __restrict__ alpha,
      float* __restrict__ out_ctx) {
    int b = blockIdx.x, t = threadIdx.x, w = t >> 5, lane = t & 31;
    int len = slen[b];
    int len_eff = (len == 0) ? NS : len;
    int nval = (len_eff + POS_PER_BLOCK - 1) / POS_PER_BLOCK;   // valid chunks

    __shared__ float sM[NCHUNK], sL[NCHUNK];
    __shared__ __align__(16) float sm[ND];
    if (t < NCHUNK) {
        sM[t] = (t < nval) ? g_PM[b * NCHUNK + t] : -1e30f;
        sL[t] = (t < nval) ? g_PL[b * NCHUNK + t] : 0.f;
    }
    __syncthreads();
    float Mg = sM[0];
    #pragma unroll 8
    for (int j = 1; j < NCHUNK; j++) Mg = fmaxf(Mg, sM[j]);
    float Lg = 0.f;
    #pragma unroll 8
    for (int j = 0; j < NCHUNK; j++) Lg = fmaf(sL[j], __expf(sM[j] - Mg), Lg);
    float m = 0.f;
    #pragma unroll 8
    for (int j = 0; j < nval; j++)
        m = fmaf(__expf(sM[j] - Mg), g_PA[(b * NCHUNK + j) * ND + t], m);
    float Rinv = 1.f / Lg;
    m *= Rinv;
    sm[t] = m;
    __syncthreads();

    // context GEMV: warp per output row
    const float4* m4 = (const float4*)sm;
    float4 ma = m4[lane], mb = m4[lane + 32];
    #pragma unroll
    for (int d = w; d < ND; d += 8) {
        const float4* wr = (const float4*)(Wc_w + d * ND);
        float4 wa = wr[lane], wb = wr[lane + 32];
        float p = wa.x*ma.x + wa.y*ma.y + wa.z*ma.z + wa.w*ma.w
                + wb.x*mb.x + wb.y*mb.y + wb.z*mb.z + wb.w*mb.w;
        #pragma unroll
        for (int o = 16; o > 0; o >>= 1)
            p += __shfl_xor_sync(0xffffffffu, p, o);
        if (lane == 0) out_ctx[b * ND + d] = p + Wc_b[d];
    }

    // normalize this batch's alpha: 2048 float4, 8 per thread, loads 8-deep
    float4* a4 = (float4*)(alpha + (size_t)b * NS);
    float4 ev[8];
    #pragma unroll
    for (int k = 0; k < 8; k++) ev[k] = a4[k * 256 + t];
    #pragma unroll
    for (int k = 0; k < 8; k++) {
        int pos = (k * 256 + t) * 4;
        float4 o;
        if (len > 0 && pos >= len) {           // fully masked group
            o = make_float4(0.f, 0.f, 0.f, 0.f);
        } else {
            o.x = (len > 0 && pos + 0 >= len) ? 0.f : __expf(ev[k].x - Mg) * Rinv;
            o.y = (len > 0 && pos + 1 >= len) ? 0.f : __expf(ev[k].y - Mg) * Rinv;
            o.z = (len > 0 && pos + 2 >= len) ? 0.f : __expf(ev[k].z - Mg) * Rinv;
            o.w = (len > 0 && pos + 3 >= len) ? 0.f : __expf(ev[k].w - Mg) * Rinv;
        }
        a4[k * 256 + t] = o;
    }
}

// ---------------- launch ----------------
extern "C" void kernel_launch(void* const* d_in, const int* in_sizes, int n_in,
                              void* d_out, int out_size) {
    const float* hs   = (const float*)d_in[0];  // [B,S,256]
    const float* ht   = (const float*)d_in[1];  // [B,256]
    const int*   slen = (const int*)  d_in[2];  // [B]
    const float* Wa_w = (const float*)d_in[3];  // [256,256]
    const float* Wa_b = (const float*)d_in[4];  // [256]
    const float* Wc_w = (const float*)d_in[5];  // [256,256]
    const float* Wc_b = (const float*)d_in[6];  // [256]

    float* alpha = (float*)d_out;                    // [B,S]
    float* ctx   = (float*)d_out + (size_t)NB * NS;  // [B,256]

    k_pre<<<NB, 1024>>>(ht, Wa_w, Wa_b);
    dim3 grid2(NCHUNK, NB);
    k_main<<<grid2, 256>>>(hs, slen, alpha);
    k_fin<<<NB, 256>>>(Wc_w, Wc_b, slen, alpha, ctx);
}

// round 7
// speedup vs baseline: 1.0963x; 1.0963x over previous
#include <cuda_runtime.h>
#include <math.h>
#include <stdint.h>

#define NB 32
#define NS 8192
#define ND 256
#define NCHUNK 64          // blocks per batch in main pass
#define POS_PER_BLOCK 128  // rows per block
#define TILE_ROWS 16       // rows per cp.async tile
#define NTILES (POS_PER_BLOCK / TILE_ROWS)   // 8
#define NPRE 4             // k_pre reduction split
#define EXP_OFF 48.0f      // fixed softmax offset (energies << 48+88)

// ---------------- scratch (no allocation allowed) ----------------
__device__ float g_Vp[NB * NPRE * ND];     // partial v[b] = Wa_w^T ht[b]
__device__ float g_c0[NB];                 // ht[b] . Wa_b
__device__ float g_PL[NB * NCHUNK];        // per-block partial sum (fixed offset)
__device__ float g_PA[NB * NCHUNK * ND];   // per-block partial weighted row-sum

// ---------------- cp.async helpers ----------------
__device__ __forceinline__ void cp16(uint32_t dst, const void* src) {
    asm volatile("cp.async.cg.shared.global [%0], [%1], 16;\n" :: "r"(dst), "l"(src));
}
__device__ __forceinline__ void cp_commit() {
    asm volatile("cp.async.commit_group;\n" ::: "memory");
}
template <int N>
__device__ __forceinline__ void cp_wait() {
    asm volatile("cp.async.wait_group %0;\n" :: "n"(N) : "memory");
}

// ---------------- K1: partial v[b], c0[b] (4-way split over d) -----------
__global__ void __launch_bounds__(256)
k_pre(const float* __restrict__ ht,
      const float* __restrict__ Wa_w,
      const float* __restrict__ Wa_b) {
    int g = blockIdx.x, b = blockIdx.y, t = threadIdx.x;
    __shared__ float sh[64];
    if (t < 64) sh[t] = ht[b * ND + g * 64 + t];
    __syncthreads();
    const float* Wp = Wa_w + (size_t)(g * 64) * ND + t;
    float acc = 0.f;
    #pragma unroll 16
    for (int d = 0; d < 64; d++)
        acc = fmaf(sh[d], Wp[(size_t)d * ND], acc);
    g_Vp[(b * NPRE + g) * ND + t] = acc;

    if (g == 0) {   // c0 = ht . Wa_b
        __shared__ float red[ND];
        red[t] = ht[b * ND + t] * Wa_b[t];
        __syncthreads();
        for (int s = 128; s > 0; s >>= 1) {
            if (t < s) red[t] += red[t + s];
            __syncthreads();
        }
        if (t == 0) g_c0[b] = red[0];
    }
}

// ---------------- K2: cp.async-pipelined energy+softmax+weighted-sum ------
__global__ void __launch_bounds__(256, 4)
k_main(const float* __restrict__ hs, const int* __restrict__ slen,
       float* __restrict__ alpha) {
    __shared__ __align__(16) float sbuf[2][TILE_ROWS * ND];   // 2 x 16KB
    __shared__ float sA[8][ND];                                // 8KB
    __shared__ float sL[8];

    int chunk = blockIdx.x, b = blockIdx.y;
    int tid = threadIdx.x, w = tid >> 5, lane = tid & 31;
    int len = slen[b];
    int len_eff = (len == 0) ? NS : len;
    float off = (len == 0) ? -10000.f : EXP_OFF;

    if (chunk * POS_PER_BLOCK >= len_eff) return;

    const float* gsrc = hs + ((size_t)b * NS + chunk * POS_PER_BLOCK) * ND;
    uint32_t sb = (uint32_t)__cvta_generic_to_shared(&sbuf[0][0]);

    // stage tile 0
    {
        uint32_t dst = sb;
        const char* src = (const char*)gsrc;
        #pragma unroll
        for (int k = 0; k < 4; k++)
            cp16(dst + (tid + k * 256) * 16, src + (tid + k * 256) * 16);
        cp_commit();
    }

    // fold the 4 v-partials (L2-hot) while tile 0 is in flight
    float c0 = g_c0[b];
    const float4* vp = (const float4*)(g_Vp + (size_t)b * NPRE * ND);
    float4 va = vp[lane], vb = vp[lane + 32];
    #pragma unroll
    for (int g = 1; g < NPRE; g++) {
        float4 pa = vp[g * 64 + lane], pb = vp[g * 64 + lane + 32];
        va.x += pa.x; va.y += pa.y; va.z += pa.z; va.w += pa.w;
        vb.x += pb.x; vb.y += pb.y; vb.z += pb.z; vb.w += pb.w;
    }

    float Lsum = 0.f;
    float4 Aa = make_float4(0.f, 0.f, 0.f, 0.f);
    float4 Ab = make_float4(0.f, 0.f, 0.f, 0.f);

    int s0 = chunk * POS_PER_BLOCK;

    #pragma unroll 1
    for (int t = 0; t < NTILES; t++) {
        if (t < NTILES - 1) {            // stage next tile into other buffer
            uint32_t dst = sb + ((t + 1) & 1) * (TILE_ROWS * ND * 4);
            const char* src = (const char*)(gsrc + (t + 1) * TILE_ROWS * ND);
            #pragma unroll
            for (int k = 0; k < 4; k++)
                cp16(dst + (tid + k * 256) * 16, src + (tid + k * 256) * 16);
            cp_commit();
            cp_wait<1>();
        } else {
            cp_wait<0>();
        }
        __syncthreads();

        // compute: warp w handles rows 2w, 2w+1 of this tile
        const float* sp = sbuf[t & 1] + (2 * w) * ND;
        float4 r1a = ((const float4*)sp)[lane];
        float4 r1b = ((const float4*)sp)[lane + 32];
        float4 r2a = ((const float4*)sp)[64 + lane];
        float4 r2b = ((const float4*)sp)[64 + lane + 32];

        float p1 = r1a.x*va.x + r1a.y*va.y + r1a.z*va.z + r1a.w*va.w
                 + r1b.x*vb.x + r1b.y*vb.y + r1b.z*vb.z + r1b.w*vb.w;
        float p2 = r2a.x*va.x + r2a.y*va.y + r2a.z*va.z + r2a.w*va.w
                 + r2b.x*vb.x + r2b.y*vb.y + r2b.z*vb.z + r2b.w*vb.w;
        #pragma unroll
        for (int o = 16; o > 0; o >>= 1) {
            p1 += __shfl_xor_sync(0xffffffffu, p1, o);
            p2 += __shfl_xor_sync(0xffffffffu, p2, o);
        }
        int s = s0 + t * TILE_ROWS + 2 * w;
        float e1 = p1 + c0, e2 = p2 + c0;
        e1 = (e1 > 0.f) ? e1 : 0.2f * e1;            // leaky relu
        e2 = (e2 > 0.f) ? e2 : 0.2f * e2;
        if (s + 0 >= len) e1 = -10000.f;             // length mask
        if (s + 1 >= len) e2 = -10000.f;
        if (lane == 0)
            *(float2*)(alpha + (size_t)b * NS + s) = make_float2(e1, e2);

        float q1 = __expf(e1 - off);                 // fixed offset, no online max
        float q2 = __expf(e2 - off);
        Lsum += q1 + q2;
        Aa.x = fmaf(q2, r2a.x, fmaf(q1, r1a.x, Aa.x));
        Aa.y = fmaf(q2, r2a.y, fmaf(q1, r1a.y, Aa.y));
        Aa.z = fmaf(q2, r2a.z, fmaf(q1, r1a.z, Aa.z));
        Aa.w = fmaf(q2, r2a.w, fmaf(q1, r1a.w, Aa.w));
        Ab.x = fmaf(q2, r2b.x, fmaf(q1, r1b.x, Ab.x));
        Ab.y = fmaf(q2, r2b.y, fmaf(q1, r1b.y, Ab.y));
        Ab.z = fmaf(q2, r2b.z, fmaf(q1, r1b.z, Ab.z));
        Ab.w = fmaf(q2, r2b.w, fmaf(q1, r1b.w, Ab.w));
        __syncthreads();
    }

    // combine 8 warps: plain sums (shared fixed offset)
    float* arow = sA[w];
    arow[lane * 4 + 0] = Aa.x; arow[lane * 4 + 1] = Aa.y;
    arow[lane * 4 + 2] = Aa.z; arow[lane * 4 + 3] = Aa.w;
    arow[128 + lane * 4 + 0] = Ab.x; arow[128 + lane * 4 + 1] = Ab.y;
    arow[128 + lane * 4 + 2] = Ab.z; arow[128 + lane * 4 + 3] = Ab.w;
    if (lane == 0) sL[w] = Lsum;
    __syncthreads();

    float acc = 0.f;
    #pragma unroll
    for (int j = 0; j < 8; j++) acc += sA[j][tid];
    int pid = b * NCHUNK + chunk;
    g_PA[pid * ND + tid] = acc;
    if (tid == 0) {
        float lb = 0.f;
        #pragma unroll
        for (int j = 0; j < 8; j++) lb += sL[j];
        g_PL[pid] = lb;
    }
}

// ---------------- K3: combine + context GEMV + alpha normalize -----------
__global__ void __launch_bounds__(256)
k_fin(const float* __restrict__ Wc_w, const float* __restrict__ Wc_b,
      const int* __restrict__ slen, float* __restrict__ alpha,
      float* __restrict__ out_ctx) {
    int b = blockIdx.x, t = threadIdx.x, w = t >> 5, lane = t & 31;
    int len = slen[b];
    int len_eff = (len == 0) ? NS : len;
    float off = (len == 0) ? -10000.f : EXP_OFF;
    int nval = (len_eff + POS_PER_BLOCK - 1) / POS_PER_BLOCK;

    __shared__ float sLs[NCHUNK];
    __shared__ __align__(16) float sm[ND];
    if (t < NCHUNK) sLs[t] = (t < nval) ? g_PL[b * NCHUNK + t] : 0.f;
    __syncthreads();
    float Lg = 0.f;
    #pragma unroll 8
    for (int j = 0; j < NCHUNK; j++) Lg += sLs[j];
    float m = 0.f;
    #pragma unroll 8
    for (int j = 0; j < nval; j++)
        m += g_PA[(b * NCHUNK + j) * ND + t];
    float Rinv = 1.f / Lg;
    m *= Rinv;
    sm[t] = m;
    __syncthreads();

    // context GEMV: warp per output row
    const float4* m4 = (const float4*)sm;
    float4 ma = m4[lane], mb = m4[lane + 32];
    #pragma unroll
    for (int d = w; d < ND; d += 8) {
        const float4* wr = (const float4*)(Wc_w + d * ND);
        float4 wa = wr[lane], wb = wr[lane + 32];
        float p = wa.x*ma.x + wa.y*ma.y + wa.z*ma.z + wa.w*ma.w
                + wb.x*mb.x + wb.y*mb.y + wb.z*mb.z + wb.w*mb.w;
        #pragma unroll
        for (int o = 16; o > 0; o >>= 1)
            p += __shfl_xor_sync(0xffffffffu, p, o);
        if (lane == 0) out_ctx[b * ND + d] = p + Wc_b[d];
    }

    // normalize this batch's alpha: 2048 float4, 8 per thread
    float4* a4 = (float4*)(alpha + (size_t)b * NS);
    float4 ev[8];
    #pragma unroll
    for (int k = 0; k < 8; k++) ev[k] = a4[k * 256 + t];
    #pragma unroll
    for (int k = 0; k < 8; k++) {
        int pos = (k * 256 + t) * 4;
        float4 o;
        if (len > 0 && pos >= len) {
            o = make_float4(0.f, 0.f, 0.f, 0.f);
        } else {
            o.x = (len > 0 && pos + 0 >= len) ? 0.f : __expf(ev[k].x - off) * Rinv;
            o.y = (len > 0 && pos + 1 >= len) ? 0.f : __expf(ev[k].y - off) * Rinv;
            o.z = (len > 0 && pos + 2 >= len) ? 0.f : __expf(ev[k].z - off) * Rinv;
            o.w = (len > 0 && pos + 3 >= len) ? 0.f : __expf(ev[k].w - off) * Rinv;
        }
        a4[k * 256 + t] = o;
    }
}

// ---------------- launch ----------------
extern "C" void kernel_launch(void* const* d_in, const int* in_sizes, int n_in,
                              void* d_out, int out_size) {
    const float* hs   = (const float*)d_in[0];  // [B,S,256]
    const float* ht   = (const float*)d_in[1];  // [B,256]
    const int*   slen = (const int*)  d_in[2];  // [B]
    const float* Wa_w = (const float*)d_in[3];  // [256,256]
    const float* Wa_b = (const float*)d_in[4];  // [256]
    const float* Wc_w = (const float*)d_in[5];  // [256,256]
    const float* Wc_b = (const float*)d_in[6];  // [256]

    float* alpha = (float*)d_out;                    // [B,S]
    float* ctx   = (float*)d_out + (size_t)NB * NS;  // [B,256]

    dim3 grid1(NPRE, NB);
    k_pre<<<grid1, 256>>>(ht, Wa_w, Wa_b);
    dim3 grid2(NCHUNK, NB);
    k_main<<<grid2, 256>>>(hs, slen, alpha);
    k_fin<<<NB, 256>>>(Wc_w, Wc_b, slen, alpha, ctx);
}